// round 1
// baseline (speedup 1.0000x reference)
#include <cuda_runtime.h>
#include <cuda_bf16.h>
#include <cstdint>

// Problem constants
// B=512, N=200, C=512, NH=8, WS=5, HD=64
// M = B*N = 102400 tokens. QKV: [M,512]x[512,1536]; Proj: [M,512]x[512,512]
#define M_TOK   102400
#define K_DIM   512
#define N_QKV   1536
#define N_PROJ  512
#define N_HEADS 8
#define WIN     5
#define HDIM    64
#define SCALE   0.125f   // 64^-0.5

// Scratch (device globals: allocation-free per harness rules)
__device__ float g_qkv[(size_t)M_TOK * N_QKV];   // ~629 MB
__device__ float g_att[(size_t)M_TOK * N_PROJ];  // ~210 MB

// ---------------------------------------------------------------------------
// Packed f32x2 helpers (Blackwell FFMA2 — only reachable via PTX)
// ---------------------------------------------------------------------------
__device__ __forceinline__ unsigned long long pack2(float x, float y) {
    unsigned long long r;
    asm("mov.b64 %0, {%1, %2};" : "=l"(r)
        : "r"(__float_as_uint(x)), "r"(__float_as_uint(y)));
    return r;
}
__device__ __forceinline__ void unpack2(unsigned long long p, float &x, float &y) {
    unsigned int a, b;
    asm("mov.b64 {%0, %1}, %2;" : "=r"(a), "=r"(b) : "l"(p));
    x = __uint_as_float(a);
    y = __uint_as_float(b);
}
__device__ __forceinline__ void ffma2(unsigned long long &c,
                                      unsigned long long a,
                                      unsigned long long b) {
    asm("fma.rn.f32x2 %0, %1, %2, %0;" : "+l"(c) : "l"(a), "l"(b));
}

// ---------------------------------------------------------------------------
// SGEMM with bias: C[M,N] = A[M,K] * B[K,N] + bias[N]
// BM=128, BN=128, BK=16, 256 threads, 8x8 per-thread microtile via FFMA2.
// Requires M%128==0, N%128==0, K%16==0 (true for both GEMMs here).
// ---------------------------------------------------------------------------
#define BM 128
#define BN 128
#define BK 16
#define TM 8
#define TN 8

__global__ void __launch_bounds__(256, 2)
sgemm_bias_f32x2(const float* __restrict__ A, const float* __restrict__ B,
                 const float* __restrict__ bias, float* __restrict__ C,
                 int M, int N, int K) {
    __shared__ float As[BK][BM];   // transposed A tile: As[k][m]
    __shared__ float Bs[BK][BN];   // Bs[k][n]

    const int tid = threadIdx.x;
    const int tx = tid & 15;       // n-direction (16)
    const int ty = tid >> 4;       // m-direction (16)
    const int bm = blockIdx.y * BM;
    const int bn = blockIdx.x * BN;

    // A loader: 128x16 tile; thread loads 2 float4s
    const int aRow = tid >> 2;            // 0..63
    const int aCol = (tid & 3) << 2;      // 0,4,8,12
    // B loader: 16x128 tile; thread loads 2 float4s
    const int bRow = tid >> 5;            // 0..7
    const int bCol = (tid & 31) << 2;     // 0..124

    const float* Aptr = A + (size_t)(bm + aRow) * K + aCol;
    const float* Bptr = B + (size_t)bRow * N + (bn + bCol);

    // prefetch tile 0 into registers
    float4 ra0 = *(const float4*)(Aptr);
    float4 ra1 = *(const float4*)(Aptr + (size_t)64 * K);
    float4 rb0 = *(const float4*)(Bptr);
    float4 rb1 = *(const float4*)(Bptr + (size_t)8 * N);

    unsigned long long acc[TM][TN / 2];
#pragma unroll
    for (int m = 0; m < TM; ++m)
#pragma unroll
        for (int j = 0; j < TN / 2; ++j) acc[m][j] = 0ull;

    const int nIter = K / BK;
    for (int it = 0; it < nIter; ++it) {
        // registers -> shared (A transposed)
        As[aCol + 0][aRow] = ra0.x;
        As[aCol + 1][aRow] = ra0.y;
        As[aCol + 2][aRow] = ra0.z;
        As[aCol + 3][aRow] = ra0.w;
        As[aCol + 0][aRow + 64] = ra1.x;
        As[aCol + 1][aRow + 64] = ra1.y;
        As[aCol + 2][aRow + 64] = ra1.z;
        As[aCol + 3][aRow + 64] = ra1.w;
        *(float4*)&Bs[bRow][bCol]     = rb0;
        *(float4*)&Bs[bRow + 8][bCol] = rb1;
        __syncthreads();

        // prefetch next tile while computing this one
        if (it + 1 < nIter) {
            const float* An = Aptr + (size_t)(it + 1) * BK;
            const float* Bn = Bptr + (size_t)(it + 1) * BK * N;
            ra0 = *(const float4*)(An);
            ra1 = *(const float4*)(An + (size_t)64 * K);
            rb0 = *(const float4*)(Bn);
            rb1 = *(const float4*)(Bn + (size_t)8 * N);
        }

#pragma unroll
        for (int kk = 0; kk < BK; ++kk) {
            float4 a0 = *(const float4*)&As[kk][ty * TM];
            float4 a1 = *(const float4*)&As[kk][ty * TM + 4];
            const unsigned long long* bp =
                (const unsigned long long*)&Bs[kk][tx * TN];
            unsigned long long b2_0 = bp[0];
            unsigned long long b2_1 = bp[1];
            unsigned long long b2_2 = bp[2];
            unsigned long long b2_3 = bp[3];
            float av[TM] = {a0.x, a0.y, a0.z, a0.w, a1.x, a1.y, a1.z, a1.w};
#pragma unroll
            for (int m = 0; m < TM; ++m) {
                unsigned long long a2 = pack2(av[m], av[m]);
                ffma2(acc[m][0], a2, b2_0);
                ffma2(acc[m][1], a2, b2_1);
                ffma2(acc[m][2], a2, b2_2);
                ffma2(acc[m][3], a2, b2_3);
            }
        }
        __syncthreads();
    }

    // epilogue: unpack, add bias, store
    const int col = bn + tx * TN;
    float bvals[TN];
#pragma unroll
    for (int c = 0; c < TN; ++c) bvals[c] = bias[col + c];

#pragma unroll
    for (int m = 0; m < TM; ++m) {
        float o[TN];
#pragma unroll
        for (int j = 0; j < TN / 2; ++j) unpack2(acc[m][j], o[2 * j], o[2 * j + 1]);
#pragma unroll
        for (int c = 0; c < TN; ++c) o[c] += bvals[c];
        float* Cp = C + (size_t)(bm + ty * TM + m) * N + col;
        *(float4*)Cp       = make_float4(o[0], o[1], o[2], o[3]);
        *(float4*)(Cp + 4) = make_float4(o[4], o[5], o[6], o[7]);
    }
}

// ---------------------------------------------------------------------------
// Windowed attention over 5-token windows, 8 heads, HD=64.
// One block (256 thr) per window; warp h handles head h.
// Lane l owns dims {l, l+32}. qkv row layout: [q(512) | k(512) | v(512)],
// within each: h*64 + d.
// ---------------------------------------------------------------------------
__global__ void __launch_bounds__(256)
win_attn_kernel(const float* __restrict__ qkv, float* __restrict__ out) {
    const int win  = blockIdx.x;
    const int h    = threadIdx.x >> 5;
    const int lane = threadIdx.x & 31;
    const int m0   = win * WIN;

    const float* base = qkv + (size_t)m0 * N_QKV + h * HDIM;

    float q[WIN][2], k[WIN][2], v[WIN][2];
#pragma unroll
    for (int i = 0; i < WIN; ++i) {
        const float* r = base + (size_t)i * N_QKV;
        q[i][0] = r[lane];          q[i][1] = r[lane + 32];
        k[i][0] = r[512 + lane];    k[i][1] = r[512 + lane + 32];
        v[i][0] = r[1024 + lane];   v[i][1] = r[1024 + lane + 32];
    }

    // scores (all lanes end up with full value via butterfly reduce)
    float s[WIN][WIN];
#pragma unroll
    for (int i = 0; i < WIN; ++i) {
#pragma unroll
        for (int j = 0; j < WIN; ++j) {
            float p = q[i][0] * k[j][0] + q[i][1] * k[j][1];
            p += __shfl_xor_sync(0xffffffffu, p, 16);
            p += __shfl_xor_sync(0xffffffffu, p, 8);
            p += __shfl_xor_sync(0xffffffffu, p, 4);
            p += __shfl_xor_sync(0xffffffffu, p, 2);
            p += __shfl_xor_sync(0xffffffffu, p, 1);
            s[i][j] = p * SCALE;
        }
    }

    // softmax per row + weighted sum of V
#pragma unroll
    for (int i = 0; i < WIN; ++i) {
        float mx = s[i][0];
#pragma unroll
        for (int j = 1; j < WIN; ++j) mx = fmaxf(mx, s[i][j]);
        float sum = 0.0f;
#pragma unroll
        for (int j = 0; j < WIN; ++j) {
            s[i][j] = __expf(s[i][j] - mx);
            sum += s[i][j];
        }
        float inv = 1.0f / sum;
        float o0 = 0.0f, o1 = 0.0f;
#pragma unroll
        for (int j = 0; j < WIN; ++j) {
            float a = s[i][j] * inv;
            o0 += a * v[j][0];
            o1 += a * v[j][1];
        }
        float* orow = out + (size_t)(m0 + i) * N_PROJ + h * HDIM;
        orow[lane]      = o0;
        orow[lane + 32] = o1;
    }
}

// ---------------------------------------------------------------------------
// kernel_launch
// inputs: x[512,200,512], qkv_w[512,1536], qkv_b[1536], proj_w[512,512], proj_b[512]
// ---------------------------------------------------------------------------
extern "C" void kernel_launch(void* const* d_in, const int* in_sizes, int n_in,
                              void* d_out, int out_size) {
    const float* x      = (const float*)d_in[0];
    const float* qkv_w  = (const float*)d_in[1];
    const float* qkv_b  = (const float*)d_in[2];
    const float* proj_w = (const float*)d_in[3];
    const float* proj_b = (const float*)d_in[4];
    float* out = (float*)d_out;

    float* qkvp = nullptr;
    float* attp = nullptr;
    cudaGetSymbolAddress((void**)&qkvp, g_qkv);
    cudaGetSymbolAddress((void**)&attp, g_att);

    // GEMM1: [102400,512] x [512,1536] + qkv_b -> g_qkv
    {
        dim3 grid(N_QKV / BN, M_TOK / BM);
        sgemm_bias_f32x2<<<grid, 256>>>(x, qkv_w, qkv_b, qkvp,
                                        M_TOK, N_QKV, K_DIM);
    }

    // Windowed attention: g_qkv -> g_att
    {
        int n_windows = M_TOK / WIN;  // 20480
        win_attn_kernel<<<n_windows, 256>>>(qkvp, attp);
    }

    // GEMM2: [102400,512] x [512,512] + proj_b -> out
    {
        dim3 grid(N_PROJ / BN, M_TOK / BM);
        sgemm_bias_f32x2<<<grid, 256>>>(attp, proj_w, proj_b, out,
                                        M_TOK, N_PROJ, K_DIM);
    }
}

// round 3
// speedup vs baseline: 2.6196x; 2.6196x over previous
#include <cuda_runtime.h>
#include <cuda_bf16.h>
#include <cstdint>

// ---------------------------------------------------------------------------
// Problem: B=512,N=200,C=512,NH=8,WS=5,HD=64.  M=102400 tokens.
// GEMM1: [M,512]x[512,1536]+b ; windowed attn ; GEMM2: [M,512]x[512,512]+b
// Strategy: hi/lo bf16 split (3-term) on mma.sync m16n8k16 (HMMA), inputs
// pre-converted to fragment-image layout so GEMM smem reads are trivial.
// ---------------------------------------------------------------------------
#define M_TOK   102400
#define K_DIM   512
#define N_QKV   1536
#define N_PROJ  512
#define WIN     5
#define HSCALE  0.125f
#define NKC     16        // K chunks of 32
#define CH_A    8192      // 128x32 bf16 tile bytes (A image, per chunk)
#define CH_B    8192      // 32x128 bf16 tile bytes (B image, per chunk)
#define STAGE_B 32768     // Ah+Al+Bh+Bl per stage
#define NSTAGE  3

// ---------------- scratch (device globals; no allocation) ------------------
__device__ float          g_qkv[(size_t)M_TOK * N_QKV];            // 629 MB
__device__ __nv_bfloat16  gA_hi[(size_t)M_TOK * K_DIM];
__device__ __nv_bfloat16  gA_lo[(size_t)M_TOK * K_DIM];
__device__ __nv_bfloat16  gO_hi[(size_t)M_TOK * K_DIM];
__device__ __nv_bfloat16  gO_lo[(size_t)M_TOK * K_DIM];
__device__ __nv_bfloat16  gB1_hi[(size_t)K_DIM * N_QKV];
__device__ __nv_bfloat16  gB1_lo[(size_t)K_DIM * N_QKV];
__device__ __nv_bfloat16  gB2_hi[(size_t)K_DIM * N_PROJ];
__device__ __nv_bfloat16  gB2_lo[(size_t)K_DIM * N_PROJ];

// ---------------------------- helpers ---------------------------------------
__device__ __forceinline__ uint32_t smem_u32(const void* p) {
    uint32_t a;
    asm("{ .reg .u64 t; cvta.to.shared.u64 t, %1; cvt.u32.u64 %0, t; }"
        : "=r"(a) : "l"(p));
    return a;
}
__device__ __forceinline__ void cp16(uint32_t d, const void* s) {
    asm volatile("cp.async.cg.shared.global [%0], [%1], 16;"
                 :: "r"(d), "l"(s) : "memory");
}
__device__ __forceinline__ void cp_commit() {
    asm volatile("cp.async.commit_group;" ::: "memory");
}
__device__ __forceinline__ void cp_wait2() {
    asm volatile("cp.async.wait_group 2;" ::: "memory");
}
__device__ __forceinline__ void mma_bf16(float4& d, uint4 a, uint2 b) {
    asm volatile(
        "mma.sync.aligned.m16n8k16.row.col.f32.bf16.bf16.f32 "
        "{%0,%1,%2,%3},{%4,%5,%6,%7},{%8,%9},{%0,%1,%2,%3};"
        : "+f"(d.x), "+f"(d.y), "+f"(d.z), "+f"(d.w)
        : "r"(a.x), "r"(a.y), "r"(a.z), "r"(a.w), "r"(b.x), "r"(b.y));
}
__device__ __forceinline__ unsigned short bf_bits(__nv_bfloat16 h) {
    return *reinterpret_cast<unsigned short*>(&h);
}
__device__ __forceinline__ void split1(float f, unsigned short& h,
                                       unsigned short& l) {
    __nv_bfloat16 bh = __float2bfloat16(f);
    __nv_bfloat16 bl = __float2bfloat16(f - __bfloat162float(bh));
    h = bf_bits(bh);
    l = bf_bits(bl);
}

// Fragment-image addressing ---------------------------------------------------
// A image: per (m-tile 128, k-chunk 32) tile of 8KB.
//   frag (16x16) index = kf*8 + mf; within frag: thread t=(r%8)*4+(c%8)/2 holds
//   4 b32 (j = (r/8) + 2*(c/8)), halfword = c%2.  addr = frag*512 + t*16 + j*4.
// B image: per (n-tile 128, k-chunk 32) tile of 8KB.
//   frag (16k x 8n) index = kf*16 + nf; thread t = (n%8)*4 + (k%8)/2 holds
//   2 b32 (j = (k%16)/8), halfword = k%2.  addr = frag*256 + t*8 + j*4.

// ---------------------------------------------------------------------------
// conv: x [M,512] fp32 row-major -> A fragment images (hi/lo)
// ---------------------------------------------------------------------------
__global__ void __launch_bounds__(256)
conv_split_A(const float4* __restrict__ src, char* __restrict__ hi,
             char* __restrict__ lo) {
    size_t t = (size_t)blockIdx.x * 256 + threadIdx.x;   // M_TOK*128 threads
    int m = (int)(t >> 7);
    int k0 = (int)(t & 127) << 2;
    float4 v = src[t];
    unsigned short h0, l0, h1, l1, h2, l2, h3, l3;
    split1(v.x, h0, l0); split1(v.y, h1, l1);
    split1(v.z, h2, l2); split1(v.w, h3, l3);
    uint32_t ph0 = (uint32_t)h0 | ((uint32_t)h1 << 16);
    uint32_t ph1 = (uint32_t)h2 | ((uint32_t)h3 << 16);
    uint32_t pl0 = (uint32_t)l0 | ((uint32_t)l1 << 16);
    uint32_t pl1 = (uint32_t)l2 | ((uint32_t)l3 << 16);

    int kc = k0 >> 5, kin = k0 & 31;
    int kf = kin >> 4, c0 = kin & 15;
    int r = m & 15, mf = (m >> 4) & 7;
    size_t tile = ((size_t)(m >> 7) * NKC + kc) * CH_A;
    int frag = (kf * 8 + mf) * 512;
    int j = (r >> 3) + ((c0 >> 3) << 1);
    int t0 = (r & 7) * 4 + ((c0 & 7) >> 1);
    size_t a0 = tile + frag + t0 * 16 + j * 4;
    *(uint32_t*)(hi + a0)      = ph0;
    *(uint32_t*)(hi + a0 + 16) = ph1;
    *(uint32_t*)(lo + a0)      = pl0;
    *(uint32_t*)(lo + a0 + 16) = pl1;
}

// ---------------------------------------------------------------------------
// conv: W [K,N] fp32 row-major -> B fragment images (hi/lo)
// ---------------------------------------------------------------------------
__global__ void __launch_bounds__(256)
conv_split_W(const float4* __restrict__ src, char* __restrict__ hi,
             char* __restrict__ lo, int N) {
    size_t t = (size_t)blockIdx.x * 256 + threadIdx.x;   // K*N/4 threads
    int n4 = N >> 2;
    int k = (int)(t / n4);
    int n0 = (int)(t % n4) << 2;
    float4 v = src[t];
    float f[4] = {v.x, v.y, v.z, v.w};

    int kc = k >> 5;
    int kf = (k >> 4) & 1;
    int j = (k >> 3) & 1;
    int half = k & 1;
    int nf = (n0 & 127) >> 3;
    size_t base = ((size_t)(n0 >> 7) * NKC + kc) * CH_B +
                  (size_t)(kf * 16 + nf) * 256 + j * 4 + half * 2;
#pragma unroll
    for (int jn = 0; jn < 4; ++jn) {
        int n = n0 + jn;
        unsigned short hs, ls;
        split1(f[jn], hs, ls);
        int tf = (n & 7) * 4 + ((k & 7) >> 1);
        *(unsigned short*)(hi + base + tf * 8) = hs;
        *(unsigned short*)(lo + base + tf * 8) = ls;
    }
}

// ---------------------------------------------------------------------------
// HMMA split-bf16 GEMM: C[128,128] per CTA. 8 warps (4m x 2n), warp 32x64.
// 3-stage cp.async pipeline over 16 K-chunks of 32.
// ---------------------------------------------------------------------------
__global__ void __launch_bounds__(256, 2)
gemm_hmma_split(const char* __restrict__ gAh, const char* __restrict__ gAl,
                const char* __restrict__ gBh, const char* __restrict__ gBl,
                const float* __restrict__ bias, float* __restrict__ C,
                int N) {
    extern __shared__ __align__(128) char smem[];
    const int tid = threadIdx.x;
    const int lane = tid & 31, wid = tid >> 5;
    const int wm = wid & 3, wn = wid >> 1 >> 1;   // wm 0..3, wn 0..1
    const uint32_t dynB = smem_u32(smem);

    const size_t aBase = (size_t)blockIdx.y * NKC * CH_A;
    const size_t bBase = (size_t)blockIdx.x * NKC * CH_B;

    float4 acc[2][8];
#pragma unroll
    for (int mi = 0; mi < 2; ++mi)
#pragma unroll
        for (int ni = 0; ni < 8; ++ni)
            acc[mi][ni] = make_float4(0.f, 0.f, 0.f, 0.f);

    // stage issuer: 4 buffers x 8KB, each thread 2x16B per buffer
    auto issue = [&](int kc, int s) {
        const char* srcs[4] = {gAh + aBase + (size_t)kc * CH_A,
                               gAl + aBase + (size_t)kc * CH_A,
                               gBh + bBase + (size_t)kc * CH_B,
                               gBl + bBase + (size_t)kc * CH_B};
        uint32_t dst = dynB + s * STAGE_B;
#pragma unroll
        for (int b = 0; b < 4; ++b) {
#pragma unroll
            for (int i = 0; i < 2; ++i) {
                int off = (tid + i * 256) * 16;
                cp16(dst + b * 8192 + off, srcs[b] + off);
            }
        }
    };

#pragma unroll
    for (int s = 0; s < NSTAGE; ++s) {
        issue(s, s);
        cp_commit();
    }

    for (int kc = 0; kc < NKC; ++kc) {
        int s = kc % NSTAGE;
        cp_wait2();
        __syncthreads();

        const char* st = smem + s * STAGE_B;
        const char* aP[3] = {st, st, st + 8192};
        const char* bP[3] = {st + 16384, st + 24576, st + 16384};
#pragma unroll
        for (int term = 0; term < 3; ++term) {
#pragma unroll
            for (int kf = 0; kf < 2; ++kf) {
                const char* af = aP[term] + (kf * 8 + wm * 2) * 512 + lane * 16;
                uint4 a0 = *(const uint4*)af;
                uint4 a1 = *(const uint4*)(af + 512);
                const char* bf = bP[term] + (kf * 16 + wn * 8) * 256 + lane * 8;
#pragma unroll
                for (int ni = 0; ni < 8; ++ni) {
                    uint2 b = *(const uint2*)(bf + ni * 256);
                    mma_bf16(acc[0][ni], a0, b);
                    mma_bf16(acc[1][ni], a1, b);
                }
            }
        }
        __syncthreads();
        if (kc + NSTAGE < NKC) issue(kc + NSTAGE, s);
        cp_commit();
    }

    // epilogue: acc -> C (+bias)
    const int row0 = blockIdx.y * 128 + wm * 32 + (lane >> 2);
    const int col0 = blockIdx.x * 128 + wn * 64 + (lane & 3) * 2;
#pragma unroll
    for (int ni = 0; ni < 8; ++ni) {
        int c = col0 + ni * 8;
        float bx = bias[c], by = bias[c + 1];
#pragma unroll
        for (int mi = 0; mi < 2; ++mi) {
            float4 v = acc[mi][ni];
            float* p0 = C + (size_t)(row0 + mi * 16) * N + c;
            float* p1 = C + (size_t)(row0 + mi * 16 + 8) * N + c;
            *(float2*)p0 = make_float2(v.x + bx, v.y + by);
            *(float2*)p1 = make_float2(v.z + bx, v.w + by);
        }
    }
}

// ---------------------------------------------------------------------------
// Windowed attention (5-token windows, 8 heads, HD=64), one block per window.
// Emits output directly as hi/lo A-fragment images for GEMM2.
// ---------------------------------------------------------------------------
__global__ void __launch_bounds__(256)
win_attn_kernel(const float* __restrict__ qkv, char* __restrict__ oh,
                char* __restrict__ ol) {
    const int win = blockIdx.x;
    const int h = threadIdx.x >> 5;
    const int lane = threadIdx.x & 31;
    const int m0 = win * WIN;

    const float* base = qkv + (size_t)m0 * N_QKV + h * 64;

    float q[WIN][2], k[WIN][2], v[WIN][2];
#pragma unroll
    for (int i = 0; i < WIN; ++i) {
        const float* r = base + (size_t)i * N_QKV;
        q[i][0] = r[lane];        q[i][1] = r[lane + 32];
        k[i][0] = r[512 + lane];  k[i][1] = r[512 + lane + 32];
        v[i][0] = r[1024 + lane]; v[i][1] = r[1024 + lane + 32];
    }

    float s[WIN][WIN];
#pragma unroll
    for (int i = 0; i < WIN; ++i)
#pragma unroll
        for (int j = 0; j < WIN; ++j) {
            float p = q[i][0] * k[j][0] + q[i][1] * k[j][1];
            p += __shfl_xor_sync(0xffffffffu, p, 16);
            p += __shfl_xor_sync(0xffffffffu, p, 8);
            p += __shfl_xor_sync(0xffffffffu, p, 4);
            p += __shfl_xor_sync(0xffffffffu, p, 2);
            p += __shfl_xor_sync(0xffffffffu, p, 1);
            s[i][j] = p * HSCALE;
        }

    // fragment-image inner offset for element (m, kin=lane) — kin identical
    // for o0 (chunk 2h) and o1 (chunk 2h+1)
    const int kf = lane >> 4, c = lane & 15;
    const int inner = ((c & 7) >> 1) * 16 + ((c >> 3) << 1) * 4 + (c & 1) * 2;

#pragma unroll
    for (int i = 0; i < WIN; ++i) {
        float mx = s[i][0];
#pragma unroll
        for (int j = 1; j < WIN; ++j) mx = fmaxf(mx, s[i][j]);
        float sum = 0.0f;
#pragma unroll
        for (int j = 0; j < WIN; ++j) {
            s[i][j] = __expf(s[i][j] - mx);
            sum += s[i][j];
        }
        float inv = 1.0f / sum;
        float o0 = 0.0f, o1 = 0.0f;
#pragma unroll
        for (int j = 0; j < WIN; ++j) {
            float a = s[i][j] * inv;
            o0 += a * v[j][0];
            o1 += a * v[j][1];
        }
        int m = m0 + i;
        int r = m & 15, mf = (m & 127) >> 4;
        size_t tb = ((size_t)(m >> 7) * NKC + 2 * h) * CH_A +
                    (size_t)(kf * 8 + mf) * 512 +
                    (size_t)((r & 7) * 4) * 16 + (size_t)(r >> 3) * 4 + inner;
        unsigned short hs, ls;
        split1(o0, hs, ls);
        *(unsigned short*)(oh + tb) = hs;
        *(unsigned short*)(ol + tb) = ls;
        split1(o1, hs, ls);
        *(unsigned short*)(oh + tb + CH_A) = hs;
        *(unsigned short*)(ol + tb + CH_A) = ls;
    }
}

// ---------------------------------------------------------------------------
// kernel_launch
// ---------------------------------------------------------------------------
extern "C" void kernel_launch(void* const* d_in, const int* in_sizes, int n_in,
                              void* d_out, int out_size) {
    const float* x      = (const float*)d_in[0];
    const float* qkv_w  = (const float*)d_in[1];
    const float* qkv_b  = (const float*)d_in[2];
    const float* proj_w = (const float*)d_in[3];
    const float* proj_b = (const float*)d_in[4];
    float* out = (float*)d_out;

    float* qkvp;
    char *Ah, *Al, *Oh, *Ol, *B1h, *B1l, *B2h, *B2l;
    cudaGetSymbolAddress((void**)&qkvp, g_qkv);
    cudaGetSymbolAddress((void**)&Ah, gA_hi);
    cudaGetSymbolAddress((void**)&Al, gA_lo);
    cudaGetSymbolAddress((void**)&Oh, gO_hi);
    cudaGetSymbolAddress((void**)&Ol, gO_lo);
    cudaGetSymbolAddress((void**)&B1h, gB1_hi);
    cudaGetSymbolAddress((void**)&B1l, gB1_lo);
    cudaGetSymbolAddress((void**)&B2h, gB2_hi);
    cudaGetSymbolAddress((void**)&B2l, gB2_lo);

    static bool attr_set = false;
    if (!attr_set) {
        cudaFuncSetAttribute(gemm_hmma_split,
                             cudaFuncAttributeMaxDynamicSharedMemorySize,
                             NSTAGE * STAGE_B);
        attr_set = true;
    }

    conv_split_A<<<(M_TOK * 128) / 256, 256>>>((const float4*)x, Ah, Al);
    conv_split_W<<<(K_DIM * N_QKV / 4) / 256, 256>>>((const float4*)qkv_w,
                                                     B1h, B1l, N_QKV);
    conv_split_W<<<(K_DIM * N_PROJ / 4) / 256, 256>>>((const float4*)proj_w,
                                                      B2h, B2l, N_PROJ);

    {   // GEMM1 -> g_qkv (fp32 row-major for attention)
        dim3 grid(N_QKV / 128, M_TOK / 128);
        gemm_hmma_split<<<grid, 256, NSTAGE * STAGE_B>>>(Ah, Al, B1h, B1l,
                                                         qkv_b, qkvp, N_QKV);
    }

    win_attn_kernel<<<M_TOK / WIN, 256>>>(qkvp, Oh, Ol);

    {   // GEMM2 -> out
        dim3 grid(N_PROJ / 128, M_TOK / 128);
        gemm_hmma_split<<<grid, 256, NSTAGE * STAGE_B>>>(Oh, Ol, B2h, B2l,
                                                         proj_b, out, N_PROJ);
    }
}